// round 2
// baseline (speedup 1.0000x reference)
#include <cuda_runtime.h>
#include <math.h>

// Problem dims
#define NI 32
#define HD 64
#define WD 64
#define CI 128
#define CM 256
#define MROWS (NI*HD*WD)   // 131072

// Scratch for the yat-conv intermediate y: [N,H,W,256] fp32 = 134 MB.
// Device global (no runtime allocation, per harness rules).
__device__ float g_y[(size_t)MROWS * CM];

// ---------------------------------------------------------------------------
// Kernel 1: fused YAT conv.
//   dot  = implicit GEMM: M=131072 (n,h,w), N=256 (cout), K=1152 (kh,kw,cin)
//   asum = sum over patch of x^2  (folded into A-fragment reads)
//   bsum = sum over kernel of w^2 (folded into B-fragment reads)
//   y    = dot^2 / (asum + bsum - 2 dot + 1e-5) * (16/log1p(256))^alpha
// ---------------------------------------------------------------------------
__global__ __launch_bounds__(256)
void k1_yat(const float* __restrict__ x, const float* __restrict__ wy,
            const float* __restrict__ alphap)
{
    __shared__ float As[2][16][132];   // K-major, M across (padded)
    __shared__ float Bs[2][16][132];   // K-major, N across (padded)

    const int tid    = threadIdx.x;
    const int m_base = blockIdx.y * 128;
    const int c_base = blockIdx.x * 128;

    // A-load mapping: 128 rows x 4 float4 (K dir) = 512 float4, 2 per thread
    const int a_m = tid >> 2;          // 0..63 (+64 on 2nd)
    const int a_k = (tid & 3) * 4;     // 0,4,8,12
    // B-load mapping: 16 rows x 32 float4 = 512 float4, 2 per thread
    const int b_k = tid >> 5;          // 0..7 (+8 on 2nd)
    const int b_c = (tid & 31) * 4;    // 0..124
    const int ty  = tid >> 4, tx = tid & 15;

    float acc[8][8];
    #pragma unroll
    for (int i = 0; i < 8; i++)
        #pragma unroll
        for (int j = 0; j < 8; j++) acc[i][j] = 0.f;
    float asum[8] = {0.f,0.f,0.f,0.f,0.f,0.f,0.f,0.f};
    float bsum[8] = {0.f,0.f,0.f,0.f,0.f,0.f,0.f,0.f};

    // Per-row spatial coords for the two A rows this thread loads
    int n0[2], h0[2], w0[2];
    #pragma unroll
    for (int r = 0; r < 2; r++) {
        int m = m_base + a_m + r * 64;
        n0[r] = m >> 12; h0[r] = (m >> 6) & 63; w0[r] = m & 63;
    }

    const int NCH = (9 * CI) / 16;   // 72 K-chunks

    float4 ar[2], br[2];

    auto gload = [&](int chunk) {
        int kb  = chunk << 4;
        int khw = kb >> 7;             // 0..8  (kh*3+kw)
        int c0  = kb & 127;            // cin base within this khw
        int dh  = khw / 3 - 1;
        int dw  = khw - (khw / 3) * 3 - 1;
        #pragma unroll
        for (int r = 0; r < 2; r++) {
            int hh = h0[r] + dh, ww = w0[r] + dw;
            float4 v = make_float4(0.f, 0.f, 0.f, 0.f);
            if ((unsigned)hh < (unsigned)HD && (unsigned)ww < (unsigned)WD)
                v = *reinterpret_cast<const float4*>(
                        x + (((n0[r] * HD + hh) * WD + ww) * CI + c0 + a_k));
            ar[r] = v;
        }
        const float* bp = wy + (khw * CI + c0 + b_k) * CM + c_base + b_c;
        br[0] = *reinterpret_cast<const float4*>(bp);
        br[1] = *reinterpret_cast<const float4*>(bp + 8 * CM);
    };

    auto sstore = [&](int buf) {
        #pragma unroll
        for (int r = 0; r < 2; r++) {
            As[buf][a_k + 0][a_m + r * 64] = ar[r].x;
            As[buf][a_k + 1][a_m + r * 64] = ar[r].y;
            As[buf][a_k + 2][a_m + r * 64] = ar[r].z;
            As[buf][a_k + 3][a_m + r * 64] = ar[r].w;
            *reinterpret_cast<float4*>(&Bs[buf][b_k + r * 8][b_c]) = br[r];
        }
    };

    auto comp = [&](int buf) {
        #pragma unroll
        for (int kk = 0; kk < 16; kk++) {
            float af[8], bf[8];
            *reinterpret_cast<float4*>(af)     = *reinterpret_cast<const float4*>(&As[buf][kk][ty * 8]);
            *reinterpret_cast<float4*>(af + 4) = *reinterpret_cast<const float4*>(&As[buf][kk][ty * 8 + 4]);
            *reinterpret_cast<float4*>(bf)     = *reinterpret_cast<const float4*>(&Bs[buf][kk][tx * 8]);
            *reinterpret_cast<float4*>(bf + 4) = *reinterpret_cast<const float4*>(&Bs[buf][kk][tx * 8 + 4]);
            #pragma unroll
            for (int i = 0; i < 8; i++) asum[i] += af[i] * af[i];
            #pragma unroll
            for (int j = 0; j < 8; j++) bsum[j] += bf[j] * bf[j];
            #pragma unroll
            for (int i = 0; i < 8; i++)
                #pragma unroll
                for (int j = 0; j < 8; j++)
                    acc[i][j] += af[i] * bf[j];
        }
    };

    gload(0);
    sstore(0);
    __syncthreads();
    int buf = 0;
    for (int c = 0; c < NCH; c++) {
        if (c + 1 < NCH) gload(c + 1);
        comp(buf);
        if (c + 1 < NCH) {
            sstore(buf ^ 1);
            __syncthreads();
            buf ^= 1;
        }
    }

    // Epilogue: yat nonlinearity -> g_y
    const float alpha = alphap[0];
    const float scale = powf(16.0f / log1pf(256.0f), alpha);  // sqrt(256)=16
    #pragma unroll
    for (int i = 0; i < 8; i++) {
        size_t m = (size_t)(m_base + ty * 8 + i);
        float* dst = g_y + m * CM + c_base + tx * 8;
        float4 o0, o1;
        float v[8];
        #pragma unroll
        for (int j = 0; j < 8; j++) {
            float d    = acc[i][j];
            float dist = asum[i] + bsum[j] - 2.0f * d + 1e-5f;
            v[j] = d * d / dist * scale;
        }
        o0 = make_float4(v[0], v[1], v[2], v[3]);
        o1 = make_float4(v[4], v[5], v[6], v[7]);
        *reinterpret_cast<float4*>(dst)     = o0;
        *reinterpret_cast<float4*>(dst + 4) = o1;
    }
}

// ---------------------------------------------------------------------------
// Kernel 2: lin conv (K=2304 over g_y) + 1x1 residual (K=128 over x)
//           + fused 2x2 avg-pool epilogue.
// M-tile of 128 = one even-h row-pair (2 x 64 spatial), so pooling is
// intra-CTA: stage z in smem, reduce 2x2, write [n, h/2, 0..31, ctile].
// ---------------------------------------------------------------------------
__global__ __launch_bounds__(256)
void k2_lin(const float* __restrict__ x, const float* __restrict__ wl,
            const float* __restrict__ wp, float* __restrict__ out)
{
    extern __shared__ float sm[];
    // GEMM buffers: As [2][16][132] then Bs [2][16][132]
    float* Asb = sm;
    float* Bsb = sm + 2 * 16 * 132;
    // Epilogue reuses sm as z[128][132]

    const int tid    = threadIdx.x;
    const int m_base = blockIdx.y * 128;
    const int c_base = blockIdx.x * 128;

    const int a_m = tid >> 2;
    const int a_k = (tid & 3) * 4;
    const int b_k = tid >> 5;
    const int b_c = (tid & 31) * 4;
    const int ty  = tid >> 4, tx = tid & 15;

    float acc[8][8];
    #pragma unroll
    for (int i = 0; i < 8; i++)
        #pragma unroll
        for (int j = 0; j < 8; j++) acc[i][j] = 0.f;

    int n0[2], h0[2], w0[2];
    #pragma unroll
    for (int r = 0; r < 2; r++) {
        int m = m_base + a_m + r * 64;
        n0[r] = m >> 12; h0[r] = (m >> 6) & 63; w0[r] = m & 63;
    }

    const int NC1 = (9 * CM) / 16;   // 144 chunks for the 3x3x256 conv
    const int NCT = NC1 + CI / 16;   // +8 chunks for the 1x1 residual

    float4 ar[2], br[2];

    auto gload = [&](int chunk) {
        if (chunk < NC1) {
            int kb  = chunk << 4;
            int khw = kb >> 8;         // 0..8
            int c0  = kb & 255;
            int dh  = khw / 3 - 1;
            int dw  = khw - (khw / 3) * 3 - 1;
            #pragma unroll
            for (int r = 0; r < 2; r++) {
                int hh = h0[r] + dh, ww = w0[r] + dw;
                float4 v = make_float4(0.f, 0.f, 0.f, 0.f);
                if ((unsigned)hh < (unsigned)HD && (unsigned)ww < (unsigned)WD)
                    v = *reinterpret_cast<const float4*>(
                            g_y + ((size_t)((n0[r] * HD + hh) * WD + ww)) * CM + c0 + a_k);
                ar[r] = v;
            }
            const float* bp = wl + (size_t)((khw * CM + c0 + b_k)) * CM + c_base + b_c;
            br[0] = *reinterpret_cast<const float4*>(bp);
            br[1] = *reinterpret_cast<const float4*>(bp + 8 * CM);
        } else {
            int cc = (chunk - NC1) << 4;   // cin base 0..112
            #pragma unroll
            for (int r = 0; r < 2; r++) {
                size_t m = (size_t)(m_base + a_m + r * 64);
                ar[r] = *reinterpret_cast<const float4*>(x + m * CI + cc + a_k);
            }
            const float* bp = wp + (cc + b_k) * CM + c_base + b_c;
            br[0] = *reinterpret_cast<const float4*>(bp);
            br[1] = *reinterpret_cast<const float4*>(bp + 8 * CM);
        }
    };

    auto sstore = [&](int buf) {
        float (*As)[16][132] = reinterpret_cast<float (*)[16][132]>(Asb);
        float (*Bs)[16][132] = reinterpret_cast<float (*)[16][132]>(Bsb);
        #pragma unroll
        for (int r = 0; r < 2; r++) {
            As[buf][a_k + 0][a_m + r * 64] = ar[r].x;
            As[buf][a_k + 1][a_m + r * 64] = ar[r].y;
            As[buf][a_k + 2][a_m + r * 64] = ar[r].z;
            As[buf][a_k + 3][a_m + r * 64] = ar[r].w;
            *reinterpret_cast<float4*>(&Bs[buf][b_k + r * 8][b_c]) = br[r];
        }
    };

    auto comp = [&](int buf) {
        float (*As)[16][132] = reinterpret_cast<float (*)[16][132]>(Asb);
        float (*Bs)[16][132] = reinterpret_cast<float (*)[16][132]>(Bsb);
        #pragma unroll
        for (int kk = 0; kk < 16; kk++) {
            float af[8], bf[8];
            *reinterpret_cast<float4*>(af)     = *reinterpret_cast<const float4*>(&As[buf][kk][ty * 8]);
            *reinterpret_cast<float4*>(af + 4) = *reinterpret_cast<const float4*>(&As[buf][kk][ty * 8 + 4]);
            *reinterpret_cast<float4*>(bf)     = *reinterpret_cast<const float4*>(&Bs[buf][kk][tx * 8]);
            *reinterpret_cast<float4*>(bf + 4) = *reinterpret_cast<const float4*>(&Bs[buf][kk][tx * 8 + 4]);
            #pragma unroll
            for (int i = 0; i < 8; i++)
                #pragma unroll
                for (int j = 0; j < 8; j++)
                    acc[i][j] += af[i] * bf[j];
        }
    };

    gload(0);
    sstore(0);
    __syncthreads();
    int buf = 0;
    for (int c = 0; c < NCT; c++) {
        if (c + 1 < NCT) gload(c + 1);
        comp(buf);
        if (c + 1 < NCT) {
            sstore(buf ^ 1);
            __syncthreads();
            buf ^= 1;
        }
    }

    // --- Epilogue: stage z tile to smem, 2x2 avg-pool, write out ---
    __syncthreads();                       // everyone done with GEMM buffers
    #pragma unroll
    for (int i = 0; i < 8; i++) {
        int row = ty * 8 + i;              // 0..127 local spatial (hl*64 + w)
        *reinterpret_cast<float4*>(&sm[row * 132 + tx * 8]) =
            make_float4(acc[i][0], acc[i][1], acc[i][2], acc[i][3]);
        *reinterpret_cast<float4*>(&sm[row * 132 + tx * 8 + 4]) =
            make_float4(acc[i][4], acc[i][5], acc[i][6], acc[i][7]);
    }
    __syncthreads();

    const int n  = m_base >> 12;
    const int hp = ((m_base >> 6) & 63) >> 1;   // pooled h (m_base's h is even)

    #pragma unroll
    for (int it = 0; it < 4; it++) {
        int idx = tid + it * 256;          // 0..1023
        int pw  = idx >> 5;                // 0..31 pooled w
        int ch  = (idx & 31) * 4;          // 0..124 channel (float4)
        const float4 z0 = *reinterpret_cast<const float4*>(&sm[(2 * pw    ) * 132 + ch]);
        const float4 z1 = *reinterpret_cast<const float4*>(&sm[(2 * pw + 1) * 132 + ch]);
        const float4 z2 = *reinterpret_cast<const float4*>(&sm[(64 + 2 * pw    ) * 132 + ch]);
        const float4 z3 = *reinterpret_cast<const float4*>(&sm[(64 + 2 * pw + 1) * 132 + ch]);
        float4 o;
        o.x = 0.25f * (z0.x + z1.x + z2.x + z3.x);
        o.y = 0.25f * (z0.y + z1.y + z2.y + z3.y);
        o.z = 0.25f * (z0.z + z1.z + z2.z + z3.z);
        o.w = 0.25f * (z0.w + z1.w + z2.w + z3.w);
        size_t oi = ((size_t)((n * 32 + hp) * 32 + pw)) * 256 + c_base + ch;
        *reinterpret_cast<float4*>(out + oi) = o;
    }
}

// ---------------------------------------------------------------------------
extern "C" void kernel_launch(void* const* d_in, const int* in_sizes, int n_in,
                              void* d_out, int out_size)
{
    const float* x  = (const float*)d_in[0];   // [32,64,64,128]
    const float* wy = (const float*)d_in[1];   // [3,3,128,256]
    const float* al = (const float*)d_in[2];   // [1]
    const float* wl = (const float*)d_in[3];   // [3,3,256,256]
    const float* wp = (const float*)d_in[4];   // [1,1,128,256]
    float* out = (float*)d_out;                // [32,32,32,256]

    const int smem2 = 128 * 132 * 4;           // 67584 B (> 48K, opt-in)
    cudaFuncSetAttribute(k2_lin, cudaFuncAttributeMaxDynamicSharedMemorySize, smem2);

    dim3 grid(2, 1024);   // (cout tiles, M tiles)
    k1_yat<<<grid, 256>>>(x, wy, al);
    k2_lin<<<grid, 256, smem2>>>(x, wl, wp, out);
}

// round 4
// speedup vs baseline: 3.5904x; 3.5904x over previous
#include <cuda_runtime.h>
#include <cstdint>
#include <math.h>

#define K1T 1152
#define K2T 2432
#define NCH1 36
#define NCH2 76

__device__ float g_y[(size_t)131072 * 256];
__device__ float g_xr[(size_t)131072 * 128];
__device__ float g_sq[131072];
__device__ float g_asum[131072];
__device__ float g_wyT[256 * K1T];
__device__ float g_wlT[256 * K2T];
__device__ float g_bsum[256];

__device__ __forceinline__ uint32_t smem_u32(const void* p) {
    uint32_t a;
    asm("{ .reg .u64 t; cvta.to.shared.u64 t, %1; cvt.u32.u64 %0, t; }" : "=r"(a) : "l"(p));
    return a;
}
__device__ __forceinline__ float tf32r(float f) {
    uint32_t u; asm("cvt.rna.tf32.f32 %0, %1;" : "=r"(u) : "f"(f));
    return __uint_as_float(u);
}
__device__ __forceinline__ void cpa16(uint32_t dst, const float* src, uint32_t sz) {
    asm volatile("cp.async.cg.shared.global [%0], [%1], 16, %2;" :: "r"(dst), "l"(src), "r"(sz));
}
#define CPA_COMMIT()  asm volatile("cp.async.commit_group;" ::: "memory")
#define CPA_WAIT(n)   asm volatile("cp.async.wait_group %0;" :: "n"(n) : "memory")

__device__ __forceinline__ void mma8(float* d, const uint32_t* a, const uint32_t* b) {
    asm volatile("mma.sync.aligned.m16n8k8.row.col.f32.tf32.tf32.f32 "
                 "{%0,%1,%2,%3}, {%4,%5,%6,%7}, {%8,%9}, {%0,%1,%2,%3};"
                 : "+f"(d[0]), "+f"(d[1]), "+f"(d[2]), "+f"(d[3])
                 : "r"(a[0]), "r"(a[1]), "r"(a[2]), "r"(a[3]), "r"(b[0]), "r"(b[1]));
}

// Per-chunk compute: As/Bs are [row][k0..31], row stride 36 floats.
__device__ __forceinline__ void compute_chunk(const float* As, const float* Bs,
                                              float acc[2][8][4], int lane, int wm, int wn)
{
    const int r = lane >> 2, cc = lane & 3;
    #pragma unroll
    for (int ks = 0; ks < 4; ks++) {
        const int k0 = ks * 8;
        const float* Ab = As + (wm * 32) * 36 + k0;
        const float* Bb = Bs + (wn * 64) * 36 + k0;
        uint32_t a[2][4], b[8][2];
        #pragma unroll
        for (int mi = 0; mi < 2; mi++) {
            a[mi][0] = __float_as_uint(Ab[(mi * 16 + r) * 36 + cc]);
            a[mi][1] = __float_as_uint(Ab[(mi * 16 + r + 8) * 36 + cc]);
            a[mi][2] = __float_as_uint(Ab[(mi * 16 + r) * 36 + cc + 4]);
            a[mi][3] = __float_as_uint(Ab[(mi * 16 + r + 8) * 36 + cc + 4]);
        }
        #pragma unroll
        for (int ni = 0; ni < 8; ni++) {
            b[ni][0] = __float_as_uint(Bb[(ni * 8 + r) * 36 + cc]);
            b[ni][1] = __float_as_uint(Bb[(ni * 8 + r) * 36 + cc + 4]);
        }
        #pragma unroll
        for (int mi = 0; mi < 2; mi++)
            #pragma unroll
            for (int ni = 0; ni < 8; ni++)
                mma8(acc[mi][ni], a[mi], b[ni]);
    }
}

// ---- prep kernels ----
__global__ __launch_bounds__(256)
void k0a_w(const float* __restrict__ wy, const float* __restrict__ wl, const float* __restrict__ wp)
{
    const int co = blockIdx.x, t = threadIdx.x;
    __shared__ float red[256];
    float s = 0.f;
    for (int k = t; k < K1T; k += 256) {
        float v = wy[(size_t)k * 256 + co];
        s += v * v;
        g_wyT[(size_t)co * K1T + k] = tf32r(v);
    }
    red[t] = s; __syncthreads();
    for (int o = 128; o > 0; o >>= 1) { if (t < o) red[t] += red[t + o]; __syncthreads(); }
    if (t == 0) g_bsum[co] = red[0];
    for (int k = t; k < K2T; k += 256) {
        float v = (k < 2304) ? wl[(size_t)k * 256 + co] : wp[(size_t)(k - 2304) * 256 + co];
        g_wlT[(size_t)co * K2T + k] = tf32r(v);
    }
}
__global__ __launch_bounds__(256)
void k0b_x(const float* __restrict__ x)
{
    const int p = blockIdx.x * 8 + (threadIdx.x >> 5), lane = threadIdx.x & 31;
    float4 v = *(const float4*)(x + (size_t)p * 128 + lane * 4);
    float s = v.x * v.x + v.y * v.y + v.z * v.z + v.w * v.w;
    #pragma unroll
    for (int o = 16; o > 0; o >>= 1) s += __shfl_xor_sync(0xffffffff, s, o);
    if (lane == 0) g_sq[p] = s;
    *(float4*)(g_xr + (size_t)p * 128 + lane * 4) =
        make_float4(tf32r(v.x), tf32r(v.y), tf32r(v.z), tf32r(v.w));
}
__global__ __launch_bounds__(256)
void k0c_asum()
{
    const int p = blockIdx.x * 256 + threadIdx.x;
    const int h = (p >> 6) & 63, w = p & 63;
    float s = 0.f;
    #pragma unroll
    for (int dh = -1; dh <= 1; dh++)
        #pragma unroll
        for (int dw = -1; dw <= 1; dw++) {
            int hh = h + dh, ww = w + dw;
            if ((unsigned)hh < 64u && (unsigned)ww < 64u)
                s += g_sq[p + dh * 64 + dw];
        }
    g_asum[p] = s;
}

// ---- k1: yat conv ----
__global__ __launch_bounds__(256, 2)
void k1_yat(const float* __restrict__ alphap)
{
    extern __shared__ float smf[];
    const uint32_t sb = smem_u32(smf);
    const int tid = threadIdx.x, lane = tid & 31, wid = tid >> 5;
    const int wm = wid >> 1, wn = wid & 1;
    const int m_base = blockIdx.y * 128, c_base = blockIdx.x * 128;
    float* sbsum = smf + 18432;
    if (tid < 128) sbsum[tid] = g_bsum[c_base + tid];

    float acc[2][8][4];
    #pragma unroll
    for (int mi = 0; mi < 2; mi++)
        #pragma unroll
        for (int ni = 0; ni < 8; ni++)
            #pragma unroll
            for (int e = 0; e < 4; e++) acc[mi][ni][e] = 0.f;

    const int c4 = tid & 7, row0 = tid >> 3;
    // stage chunk c into buffer b
    auto stage = [&](int c, int b) {
        const int khw = c >> 2, c0 = (c & 3) * 32;
        const int dh = khw / 3 - 1, dw = khw % 3 - 1;
        const uint32_t sA = sb + (b * 4608) * 4, sB = sb + (9216 + b * 4608) * 4;
        #pragma unroll
        for (int p = 0; p < 4; p++) {
            const int r = row0 + p * 32, m = m_base + r;
            const int n = m >> 12, h = (m >> 6) & 63, w = m & 63;
            const int hh = h + dh, ww = w + dw;
            const bool ok = (unsigned)hh < 64u && (unsigned)ww < 64u;
            const float* src = g_xr + (size_t)((n * 64 + (ok ? hh : 0)) * 64 + (ok ? ww : 0)) * 128 + c0 + c4 * 4;
            cpa16(sA + (r * 36 + c4 * 4) * 4, src, ok ? 16u : 0u);
            const float* bs = g_wyT + (size_t)(c_base + r) * K1T + c * 32 + c4 * 4;
            cpa16(sB + (r * 36 + c4 * 4) * 4, bs, 16u);
        }
        CPA_COMMIT();
    };

    stage(0, 0);
    for (int c = 0; c < NCH1; c++) {
        if (c + 1 < NCH1) { stage(c + 1, (c + 1) & 1); CPA_WAIT(1); }
        else CPA_WAIT(0);
        __syncthreads();
        const int b = c & 1;
        compute_chunk(smf + b * 4608, smf + 9216 + b * 4608, acc, lane, wm, wn);
        __syncthreads();
    }

    const float scale = powf(16.f / log1pf(256.f), alphap[0]);
    #pragma unroll
    for (int mi = 0; mi < 2; mi++) {
        const int r0 = wm * 32 + mi * 16 + (lane >> 2);
        const int m0 = m_base + r0, m1 = m0 + 8;
        const float as0 = g_asum[m0], as1 = g_asum[m1];
        #pragma unroll
        for (int ni = 0; ni < 8; ni++) {
            const int cl = wn * 64 + ni * 8 + (lane & 3) * 2;
            const float bs0 = sbsum[cl], bs1 = sbsum[cl + 1];
            const float* d = acc[mi][ni];
            float y00 = tf32r(d[0] * d[0] / (as0 + bs0 - 2.f * d[0] + 1e-5f) * scale);
            float y01 = tf32r(d[1] * d[1] / (as0 + bs1 - 2.f * d[1] + 1e-5f) * scale);
            float y10 = tf32r(d[2] * d[2] / (as1 + bs0 - 2.f * d[2] + 1e-5f) * scale);
            float y11 = tf32r(d[3] * d[3] / (as1 + bs1 - 2.f * d[3] + 1e-5f) * scale);
            *(float2*)(g_y + (size_t)m0 * 256 + c_base + cl) = make_float2(y00, y01);
            *(float2*)(g_y + (size_t)m1 * 256 + c_base + cl) = make_float2(y10, y11);
        }
    }
}

// ---- k2: lin conv + residual + 2x2 avg pool ----
__global__ __launch_bounds__(256, 2)
void k2_lin(float* __restrict__ out)
{
    extern __shared__ float smf[];
    const uint32_t sb = smem_u32(smf);
    const int tid = threadIdx.x, lane = tid & 31, wid = tid >> 5;
    const int wm = wid >> 1, wn = wid & 1;
    const int m_base = blockIdx.y * 128, c_base = blockIdx.x * 128;

    float acc[2][8][4];
    #pragma unroll
    for (int mi = 0; mi < 2; mi++)
        #pragma unroll
        for (int ni = 0; ni < 8; ni++)
            #pragma unroll
            for (int e = 0; e < 4; e++) acc[mi][ni][e] = 0.f;

    const int c4 = tid & 7, row0 = tid >> 3;
    auto stage = [&](int c, int b) {
        const uint32_t sA = sb + (b * 4608) * 4, sB = sb + (9216 + b * 4608) * 4;
        if (c < 72) {
            const int khw = c >> 3, c0 = (c & 7) * 32;
            const int dh = khw / 3 - 1, dw = khw % 3 - 1;
            #pragma unroll
            for (int p = 0; p < 4; p++) {
                const int r = row0 + p * 32, m = m_base + r;
                const int n = m >> 12, h = (m >> 6) & 63, w = m & 63;
                const int hh = h + dh, ww = w + dw;
                const bool ok = (unsigned)hh < 64u && (unsigned)ww < 64u;
                const float* src = g_y + (size_t)((n * 64 + (ok ? hh : 0)) * 64 + (ok ? ww : 0)) * 256 + c0 + c4 * 4;
                cpa16(sA + (r * 36 + c4 * 4) * 4, src, ok ? 16u : 0u);
                const float* bs = g_wlT + (size_t)(c_base + r) * K2T + c * 32 + c4 * 4;
                cpa16(sB + (r * 36 + c4 * 4) * 4, bs, 16u);
            }
        } else {
            const int c0 = (c - 72) * 32;
            #pragma unroll
            for (int p = 0; p < 4; p++) {
                const int r = row0 + p * 32;
                const float* src = g_xr + (size_t)(m_base + r) * 128 + c0 + c4 * 4;
                cpa16(sA + (r * 36 + c4 * 4) * 4, src, 16u);
                const float* bs = g_wlT + (size_t)(c_base + r) * K2T + c * 32 + c4 * 4;
                cpa16(sB + (r * 36 + c4 * 4) * 4, bs, 16u);
            }
        }
        CPA_COMMIT();
    };

    stage(0, 0);
    for (int c = 0; c < NCH2; c++) {
        if (c + 1 < NCH2) { stage(c + 1, (c + 1) & 1); CPA_WAIT(1); }
        else CPA_WAIT(0);
        __syncthreads();
        const int b = c & 1;
        compute_chunk(smf + b * 4608, smf + 9216 + b * 4608, acc, lane, wm, wn);
        __syncthreads();
    }

    // pool via smem z[128][132]
    __syncthreads();
    #pragma unroll
    for (int mi = 0; mi < 2; mi++) {
        const int r0 = wm * 32 + mi * 16 + (lane >> 2);
        #pragma unroll
        for (int ni = 0; ni < 8; ni++) {
            const int cl = wn * 64 + ni * 8 + (lane & 3) * 2;
            const float* d = acc[mi][ni];
            *(float2*)(smf + r0 * 132 + cl) = make_float2(d[0], d[1]);
            *(float2*)(smf + (r0 + 8) * 132 + cl) = make_float2(d[2], d[3]);
        }
    }
    __syncthreads();
    const int n = m_base >> 12, hp = ((m_base >> 6) & 63) >> 1;
    #pragma unroll
    for (int it = 0; it < 4; it++) {
        const int idx = tid + it * 256, pw = idx >> 5, ch = (idx & 31) * 4;
        float4 a0 = *(const float4*)(smf + (2 * pw) * 132 + ch);
        float4 a1 = *(const float4*)(smf + (2 * pw + 1) * 132 + ch);
        float4 a2 = *(const float4*)(smf + (64 + 2 * pw) * 132 + ch);
        float4 a3 = *(const float4*)(smf + (64 + 2 * pw + 1) * 132 + ch);
        *(float4*)(out + ((size_t)((n * 32 + hp) * 32 + pw)) * 256 + c_base + ch) =
            make_float4(0.25f * (a0.x + a1.x + a2.x + a3.x), 0.25f * (a0.y + a1.y + a2.y + a3.y),
                        0.25f * (a0.z + a1.z + a2.z + a3.z), 0.25f * (a0.w + a1.w + a2.w + a3.w));
    }
}

extern "C" void kernel_launch(void* const* d_in, const int* in_sizes, int n_in,
                              void* d_out, int out_size)
{
    const float* x  = (const float*)d_in[0];
    const float* wy = (const float*)d_in[1];
    const float* al = (const float*)d_in[2];
    const float* wl = (const float*)d_in[3];
    const float* wp = (const float*)d_in[4];
    float* out = (float*)d_out;

    cudaFuncSetAttribute(k1_yat, cudaFuncAttributeMaxDynamicSharedMemorySize, 74752);
    cudaFuncSetAttribute(k2_lin, cudaFuncAttributeMaxDynamicSharedMemorySize, 73728);

    k0a_w<<<256, 256>>>(wy, wl, wp);
    k0b_x<<<16384, 256>>>(x);
    k0c_asum<<<512, 256>>>();
    k1_yat<<<dim3(2, 1024), 256, 74752>>>(al);
    k2_lin<<<dim3(2, 1024), 256, 73728>>>(out);
}

// round 5
// speedup vs baseline: 3.9128x; 1.0898x over previous
#include <cuda_runtime.h>
#include <cstdint>
#include <math.h>

#define K1T 1152
#define K2T 2432
#define NCH1 36
#define NCH2 76

__device__ float g_y[(size_t)131072 * 256];
__device__ float g_xr[(size_t)131072 * 128];
__device__ float g_sq[131072];
__device__ float g_asum[131072];
__device__ float g_wyT[256 * K1T];
__device__ float g_wlT[256 * K2T];
__device__ float g_bsum[256];

__device__ __forceinline__ uint32_t smem_u32(const void* p) {
    uint32_t a;
    asm("{ .reg .u64 t; cvta.to.shared.u64 t, %1; cvt.u32.u64 %0, t; }" : "=r"(a) : "l"(p));
    return a;
}
__device__ __forceinline__ float tf32r(float f) {
    uint32_t u; asm("cvt.rna.tf32.f32 %0, %1;" : "=r"(u) : "f"(f));
    return __uint_as_float(u);
}
__device__ __forceinline__ int kslot(int j) { return (j < 4) ? 2 * j : 2 * j - 7; }
__device__ __forceinline__ int kperm(int k) { return (k & ~7) | kslot(k & 7); }
__device__ __forceinline__ void cpa16(uint32_t dst, const float* src, uint32_t sz) {
    asm volatile("cp.async.cg.shared.global [%0], [%1], 16, %2;" :: "r"(dst), "l"(src), "r"(sz));
}
#define CPA_COMMIT()  asm volatile("cp.async.commit_group;" ::: "memory")
#define CPA_WAIT1()   asm volatile("cp.async.wait_group 1;" ::: "memory")
#define CPA_WAIT0()   asm volatile("cp.async.wait_group 0;" ::: "memory")

__device__ __forceinline__ void mma8(float* d, const uint32_t* a, const uint32_t* b) {
    asm volatile("mma.sync.aligned.m16n8k8.row.col.f32.tf32.tf32.f32 "
                 "{%0,%1,%2,%3}, {%4,%5,%6,%7}, {%8,%9}, {%0,%1,%2,%3};"
                 : "+f"(d[0]), "+f"(d[1]), "+f"(d[2]), "+f"(d[3])
                 : "r"(a[0]), "r"(a[1]), "r"(a[2]), "r"(a[3]), "r"(b[0]), "r"(b[1]));
}

// As/Bs: 128 rows x 128B, float2 unit u swizzled by u^(4*(row&3)).
// Global k-order is pre-permuted so float2 at u=4ks+c = (k=c, k=c+4).
__device__ __forceinline__ void compute_chunk(const char* As, const char* Bs,
                                              float acc[2][8][4], int lane, int wm, int wn)
{
    const int r = lane >> 2, c = lane & 3;
    const int swz = 4 * (r & 3);
    #pragma unroll
    for (int ks = 0; ks < 4; ks++) {
        const int u = ((4 * ks + c) ^ swz) * 8;
        uint32_t a[2][4], b[8][2];
        #pragma unroll
        for (int mi = 0; mi < 2; mi++) {
            const int row0 = wm * 32 + mi * 16 + r;
            float2 lo = *(const float2*)(As + row0 * 128 + u);
            float2 hi = *(const float2*)(As + (row0 + 8) * 128 + u);
            a[mi][0] = __float_as_uint(lo.x); a[mi][1] = __float_as_uint(hi.x);
            a[mi][2] = __float_as_uint(lo.y); a[mi][3] = __float_as_uint(hi.y);
        }
        #pragma unroll
        for (int ni = 0; ni < 8; ni++) {
            float2 v = *(const float2*)(Bs + (wn * 64 + ni * 8 + r) * 128 + u);
            b[ni][0] = __float_as_uint(v.x); b[ni][1] = __float_as_uint(v.y);
        }
        #pragma unroll
        for (int mi = 0; mi < 2; mi++)
            #pragma unroll
            for (int ni = 0; ni < 8; ni++)
                mma8(acc[mi][ni], a[mi], b[ni]);
    }
}

// ---- prep ----
__global__ __launch_bounds__(256)
void k0a_w(const float* __restrict__ wy, const float* __restrict__ wl, const float* __restrict__ wp)
{
    const int co = blockIdx.x, t = threadIdx.x;
    __shared__ float red[256];
    float s = 0.f;
    for (int k = t; k < K1T; k += 256) {
        float v = wy[(size_t)k * 256 + co];
        s += v * v;
        g_wyT[(size_t)co * K1T + kperm(k)] = tf32r(v);
    }
    red[t] = s; __syncthreads();
    for (int o = 128; o > 0; o >>= 1) { if (t < o) red[t] += red[t + o]; __syncthreads(); }
    if (t == 0) g_bsum[co] = red[0];
    for (int k = t; k < K2T; k += 256) {
        float v = (k < 2304) ? wl[(size_t)k * 256 + co] : wp[(size_t)(k - 2304) * 256 + co];
        g_wlT[(size_t)co * K2T + kperm(k)] = tf32r(v);
    }
}
__global__ __launch_bounds__(256)
void k0b_x(const float* __restrict__ x)
{
    const int p = blockIdx.x * 8 + (threadIdx.x >> 5), lane = threadIdx.x & 31;
    float4 v = *(const float4*)(x + (size_t)p * 128 + lane * 4);
    float s = v.x * v.x + v.y * v.y + v.z * v.z + v.w * v.w;
    #pragma unroll
    for (int o = 16; o > 0; o >>= 1) s += __shfl_xor_sync(0xffffffff, s, o);
    if (lane == 0) g_sq[p] = s;
    float* dst = g_xr + (size_t)p * 128;
    const int ch = lane * 4;
    dst[kperm(ch)]     = tf32r(v.x);
    dst[kperm(ch + 1)] = tf32r(v.y);
    dst[kperm(ch + 2)] = tf32r(v.z);
    dst[kperm(ch + 3)] = tf32r(v.w);
}
__global__ __launch_bounds__(256)
void k0c_asum()
{
    const int p = blockIdx.x * 256 + threadIdx.x;
    const int h = (p >> 6) & 63, w = p & 63;
    float s = 0.f;
    #pragma unroll
    for (int dh = -1; dh <= 1; dh++)
        #pragma unroll
        for (int dw = -1; dw <= 1; dw++) {
            int hh = h + dh, ww = w + dw;
            if ((unsigned)hh < 64u && (unsigned)ww < 64u) s += g_sq[p + dh * 64 + dw];
        }
    g_asum[p] = s;
}

// ---- k1: yat conv ----
__global__ __launch_bounds__(256, 2)
void k1_yat(const float* __restrict__ alphap)
{
    extern __shared__ float smf[];
    const uint32_t sb = smem_u32(smf);
    const int tid = threadIdx.x, lane = tid & 31, wid = tid >> 5;
    const int wm = wid >> 1, wn = wid & 1;
    const int m_base = blockIdx.y * 128, c_base = blockIdx.x * 128;
    float* sbsum = smf + 24576;
    if (tid < 128) sbsum[tid] = g_bsum[c_base + tid];

    float acc[2][8][4];
    #pragma unroll
    for (int mi = 0; mi < 2; mi++)
        #pragma unroll
        for (int ni = 0; ni < 8; ni++)
            #pragma unroll
            for (int e = 0; e < 4; e++) acc[mi][ni][e] = 0.f;

    const int c4 = tid & 7, row0 = tid >> 3;
    auto stage = [&](int c, int b) {
        const int khw = c >> 2, c0 = (c & 3) * 32;
        const int dh = khw / 3 - 1, dw = khw % 3 - 1;
        const uint32_t sA = sb + b * 32768u, sB = sA + 16384u;
        #pragma unroll
        for (int p = 0; p < 4; p++) {
            const int r = row0 + p * 32, m = m_base + r;
            const int n = m >> 12, h = (m >> 6) & 63, w = m & 63;
            const int hh = h + dh, ww = w + dw;
            const bool ok = (unsigned)hh < 64u && (unsigned)ww < 64u;
            const uint32_t du = (uint32_t)((c4 ^ (2 * (r & 3))) * 16);
            const float* src = g_xr + (size_t)((n * 64 + (ok ? hh : 0)) * 64 + (ok ? ww : 0)) * 128 + c0 + c4 * 4;
            cpa16(sA + r * 128 + du, src, ok ? 16u : 0u);
            cpa16(sB + r * 128 + du, g_wyT + (size_t)(c_base + r) * K1T + c * 32 + c4 * 4, 16u);
        }
        CPA_COMMIT();
    };

    stage(0, 0); stage(1, 1);
    for (int c = 0; c < NCH1; c++) {
        if (c + 2 < NCH1) CPA_WAIT1(); else if (c + 1 < NCH1) CPA_WAIT1(); else CPA_WAIT0();
        __syncthreads();
        if (c + 2 < NCH1) stage(c + 2, (c + 2) % 3);
        const int b = c % 3;
        compute_chunk((const char*)smf + b * 32768, (const char*)smf + b * 32768 + 16384,
                      acc, lane, wm, wn);
    }

    const float scale = powf(16.f / log1pf(256.f), alphap[0]);
    #pragma unroll
    for (int mi = 0; mi < 2; mi++) {
        const int r0 = wm * 32 + mi * 16 + (lane >> 2);
        const int m0 = m_base + r0, m1 = m0 + 8;
        const float as0 = g_asum[m0], as1 = g_asum[m1];
        #pragma unroll
        for (int ni = 0; ni < 8; ni++) {
            const int cl = wn * 64 + ni * 8 + (lane & 3) * 2;
            const float bs0 = sbsum[cl], bs1 = sbsum[cl + 1];
            const float* d = acc[mi][ni];
            const float y00 = tf32r(d[0] * d[0] / (as0 + bs0 - 2.f * d[0] + 1e-5f) * scale);
            const float y01 = tf32r(d[1] * d[1] / (as0 + bs1 - 2.f * d[1] + 1e-5f) * scale);
            const float y10 = tf32r(d[2] * d[2] / (as1 + bs0 - 2.f * d[2] + 1e-5f) * scale);
            const float y11 = tf32r(d[3] * d[3] / (as1 + bs1 - 2.f * d[3] + 1e-5f) * scale);
            const int p0 = c_base + kperm(cl), p1 = c_base + kperm(cl + 1);
            g_y[(size_t)m0 * 256 + p0] = y00;
            g_y[(size_t)m0 * 256 + p1] = y01;
            g_y[(size_t)m1 * 256 + p0] = y10;
            g_y[(size_t)m1 * 256 + p1] = y11;
        }
    }
}

// ---- k2: lin conv + residual + 2x2 avg pool ----
__global__ __launch_bounds__(256, 2)
void k2_lin(float* __restrict__ out)
{
    extern __shared__ float smf[];
    const uint32_t sb = smem_u32(smf);
    const int tid = threadIdx.x, lane = tid & 31, wid = tid >> 5;
    const int wm = wid >> 1, wn = wid & 1;
    const int m_base = blockIdx.y * 128, c_base = blockIdx.x * 128;

    float acc[2][8][4];
    #pragma unroll
    for (int mi = 0; mi < 2; mi++)
        #pragma unroll
        for (int ni = 0; ni < 8; ni++)
            #pragma unroll
            for (int e = 0; e < 4; e++) acc[mi][ni][e] = 0.f;

    const int c4 = tid & 7, row0 = tid >> 3;
    auto stage = [&](int c, int b) {
        const uint32_t sA = sb + b * 32768u, sB = sA + 16384u;
        if (c < 72) {
            const int khw = c >> 3, c0 = (c & 7) * 32;
            const int dh = khw / 3 - 1, dw = khw % 3 - 1;
            #pragma unroll
            for (int p = 0; p < 4; p++) {
                const int r = row0 + p * 32, m = m_base + r;
                const int n = m >> 12, h = (m >> 6) & 63, w = m & 63;
                const int hh = h + dh, ww = w + dw;
                const bool ok = (unsigned)hh < 64u && (unsigned)ww < 64u;
                const uint32_t du = (uint32_t)((c4 ^ (2 * (r & 3))) * 16);
                const float* src = g_y + (size_t)((n * 64 + (ok ? hh : 0)) * 64 + (ok ? ww : 0)) * 256 + c0 + c4 * 4;
                cpa16(sA + r * 128 + du, src, ok ? 16u : 0u);
                cpa16(sB + r * 128 + du, g_wlT + (size_t)(c_base + r) * K2T + c * 32 + c4 * 4, 16u);
            }
        } else {
            const int c0 = (c - 72) * 32;
            #pragma unroll
            for (int p = 0; p < 4; p++) {
                const int r = row0 + p * 32;
                const uint32_t du = (uint32_t)((c4 ^ (2 * (r & 3))) * 16);
                cpa16(sA + r * 128 + du, g_xr + (size_t)(m_base + r) * 128 + c0 + c4 * 4, 16u);
                cpa16(sB + r * 128 + du, g_wlT + (size_t)(c_base + r) * K2T + c * 32 + c4 * 4, 16u);
            }
        }
        CPA_COMMIT();
    };

    stage(0, 0); stage(1, 1);
    for (int c = 0; c < NCH2; c++) {
        if (c + 1 < NCH2) CPA_WAIT1(); else CPA_WAIT0();
        __syncthreads();
        if (c + 2 < NCH2) stage(c + 2, (c + 2) % 3);
        const int b = c % 3;
        compute_chunk((const char*)smf + b * 32768, (const char*)smf + b * 32768 + 16384,
                      acc, lane, wm, wn);
    }

    __syncthreads();
    #pragma unroll
    for (int mi = 0; mi < 2; mi++) {
        const int r0 = wm * 32 + mi * 16 + (lane >> 2);
        #pragma unroll
        for (int ni = 0; ni < 8; ni++) {
            const int cl = wn * 64 + ni * 8 + (lane & 3) * 2;
            const float* d = acc[mi][ni];
            *(float2*)(smf + r0 * 132 + cl) = make_float2(d[0], d[1]);
            *(float2*)(smf + (r0 + 8) * 132 + cl) = make_float2(d[2], d[3]);
        }
    }
    __syncthreads();
    const int n = m_base >> 12, hp = ((m_base >> 6) & 63) >> 1;
    #pragma unroll
    for (int it = 0; it < 4; it++) {
        const int idx = tid + it * 256, pw = idx >> 5, ch = (idx & 31) * 4;
        float4 a0 = *(const float4*)(smf + (2 * pw) * 132 + ch);
        float4 a1 = *(const float4*)(smf + (2 * pw + 1) * 132 + ch);
        float4 a2 = *(const float4*)(smf + (64 + 2 * pw) * 132 + ch);
        float4 a3 = *(const float4*)(smf + (64 + 2 * pw + 1) * 132 + ch);
        *(float4*)(out + ((size_t)((n * 32 + hp) * 32 + pw)) * 256 + c_base + ch) =
            make_float4(0.25f * (a0.x + a1.x + a2.x + a3.x), 0.25f * (a0.y + a1.y + a2.y + a3.y),
                        0.25f * (a0.z + a1.z + a2.z + a3.z), 0.25f * (a0.w + a1.w + a2.w + a3.w));
    }
}

extern "C" void kernel_launch(void* const* d_in, const int* in_sizes, int n_in,
                              void* d_out, int out_size)
{
    const float* x  = (const float*)d_in[0];
    const float* wy = (const float*)d_in[1];
    const float* al = (const float*)d_in[2];
    const float* wl = (const float*)d_in[3];
    const float* wp = (const float*)d_in[4];
    float* out = (float*)d_out;

    cudaFuncSetAttribute(k1_yat, cudaFuncAttributeMaxDynamicSharedMemorySize, 98816);
    cudaFuncSetAttribute(k2_lin, cudaFuncAttributeMaxDynamicSharedMemorySize, 98304);

    k0a_w<<<256, 256>>>(wy, wl, wp);
    k0b_x<<<16384, 256>>>(x);
    k0c_asum<<<512, 256>>>();
    k1_yat<<<dim3(2, 1024), 256, 98816>>>(al);
    k2_lin<<<dim3(2, 1024), 256, 98304>>>(out);
}